// round 1
// baseline (speedup 1.0000x reference)
#include <cuda_runtime.h>
#include <cuda_fp16.h>
#include <math.h>

#define BATCH 2
#define SEQ   4096
#define DIM   128
#define SCALE 0.125f   // 64^-0.5

// ---------------- device scratch (no allocations allowed) ----------------
__device__ float  g_W[640 * 128];            // rows: 0..383 qkv, 384..511 ff1, 512..639 ff2
__device__ float  g_q[BATCH * SEQ * DIM];    // [b][n][h*64+d]
__device__ float  g_k[BATCH * SEQ * DIM];
__device__ float  g_v[BATCH * SEQ * DIM];
__device__ float  g_sq[BATCH * SEQ];
__device__ __half g_dist[(size_t)BATCH * SEQ * SEQ];   // 67 MB fp16 distances
__device__ double g_sum_spe;
__device__ float  g_inv2s2_spe;
__device__ float  g_spa[64 * 64];            // spatial mask LUT by (|dx|,|dy|)
__device__ float  g_attn[BATCH * SEQ * DIM];

// ---------------- init ----------------
__global__ void k_init() { g_sum_spe = 0.0; }

// ---------------- weight norm: W = v * g / ||v||  (row-wise, in-dim 128) ----------------
__global__ void k_weights(const float* __restrict__ vq, const float* __restrict__ gq,
                          const float* __restrict__ v1, const float* __restrict__ g1,
                          const float* __restrict__ v2, const float* __restrict__ g2) {
    int r = blockIdx.x, t = threadIdx.x;
    const float* v; float g;
    if (r < 384)      { v = vq + r * 128;        g = gq[r]; }
    else if (r < 512) { v = v1 + (r - 384) * 128; g = g1[r - 384]; }
    else              { v = v2 + (r - 512) * 128; g = g2[r - 512]; }
    float val = v[t];
    float ss = val * val;
    #pragma unroll
    for (int o = 16; o; o >>= 1) ss += __shfl_xor_sync(0xffffffffu, ss, o);
    __shared__ float ws[4];
    if ((t & 31) == 0) ws[t >> 5] = ss;
    __syncthreads();
    float tot = ws[0] + ws[1] + ws[2] + ws[3];
    g_W[r * 128 + t] = val * (g / sqrtf(tot));
}

// ---------------- qkv projection + per-token ||x||^2 ----------------
__global__ void k_qkv(const float* __restrict__ x, const float* __restrict__ bq) {
    int token = blockIdx.x, t = threadIdx.x;
    __shared__ float xs[128];
    __shared__ float ws[4];
    float xv = x[token * 128 + t];
    xs[t] = xv;
    float ss = xv * xv;
    #pragma unroll
    for (int o = 16; o; o >>= 1) ss += __shfl_xor_sync(0xffffffffu, ss, o);
    if ((t & 31) == 0) ws[t >> 5] = ss;
    __syncthreads();
    if (t == 0) g_sq[token] = ws[0] + ws[1] + ws[2] + ws[3];
    #pragma unroll 1
    for (int c = t; c < 384; c += 128) {
        const float* w = g_W + c * 128;
        float acc = bq[c];
        #pragma unroll 16
        for (int k = 0; k < 128; k++) acc = fmaf(w[k], xs[k], acc);
        float* dst = (c < 128) ? g_q : ((c < 256) ? g_k : g_v);
        dst[token * 128 + (c & 127)] = acc;
    }
}

// ---------------- pairwise distance tiles + global sum ----------------
// grid (64 jt, 64 it, BATCH), 256 threads, dyn smem = 2*128*68*4 = 69632 B
__global__ void __launch_bounds__(256) k_dist(const float* __restrict__ x) {
    extern __shared__ float sm[];
    float* xiT = sm;              // [128][68] k-major
    float* xjT = sm + 128 * 68;
    int b  = blockIdx.z;
    int i0 = blockIdx.y * 64, j0 = blockIdx.x * 64;
    int tid = threadIdx.x;
    for (int idx = tid; idx < 64 * 128; idx += 256) {
        int r = idx >> 7, k = idx & 127;
        xiT[k * 68 + r] = x[(b * SEQ + i0 + r) * 128 + k];
        xjT[k * 68 + r] = x[(b * SEQ + j0 + r) * 128 + k];
    }
    __syncthreads();
    int ty = tid >> 4, tx = tid & 15;
    float acc[4][4] = {};
    #pragma unroll 4
    for (int k = 0; k < 128; k++) {
        float4 av = *(const float4*)&xiT[k * 68 + 4 * ty];
        float4 bv = *(const float4*)&xjT[k * 68 + 4 * tx];
        float a[4] = {av.x, av.y, av.z, av.w};
        float c[4] = {bv.x, bv.y, bv.z, bv.w};
        #pragma unroll
        for (int i = 0; i < 4; i++)
            #pragma unroll
            for (int j = 0; j < 4; j++) acc[i][j] = fmaf(a[i], c[j], acc[i][j]);
    }
    float sqi[4], sqj[4];
    #pragma unroll
    for (int i = 0; i < 4; i++) {
        sqi[i] = g_sq[b * SEQ + i0 + 4 * ty + i];
        sqj[i] = g_sq[b * SEQ + j0 + 4 * tx + i];
    }
    float lsum = 0.f;
    #pragma unroll
    for (int i = 0; i < 4; i++) {
        float dv[4];
        #pragma unroll
        for (int j = 0; j < 4; j++) {
            float d2 = sqi[i] + sqj[j] - 2.f * acc[i][j];
            float dd = sqrtf(fmaxf(d2, 0.f));
            dv[j] = dd; lsum += dd;
        }
        size_t base = ((size_t)(b * SEQ + i0 + 4 * ty + i)) * SEQ + j0 + 4 * tx;
        __half2* dp = (__half2*)(g_dist + base);
        dp[0] = __floats2half2_rn(dv[0], dv[1]);
        dp[1] = __floats2half2_rn(dv[2], dv[3]);
    }
    #pragma unroll
    for (int o = 16; o; o >>= 1) lsum += __shfl_xor_sync(0xffffffffu, lsum, o);
    __shared__ float rsum[8];
    if ((tid & 31) == 0) rsum[tid >> 5] = lsum;
    __syncthreads();
    if (tid == 0) {
        float tot = 0.f;
        #pragma unroll
        for (int w = 0; w < 8; w++) tot += rsum[w];
        atomicAdd(&g_sum_spe, (double)tot);
    }
}

// ---------------- finalize sigmas + spatial LUT ----------------
__global__ void k_finalize() {
    int t = threadIdx.x;
    __shared__ double red[256];
    double local = 0.0;
    for (int idx = t; idx < 64 * 64; idx += 256) {
        int adx = idx >> 6, ady = idx & 63;
        double cx = adx ? 2.0 * (64 - adx) : 64.0;
        double cy = ady ? 2.0 * (64 - ady) : 64.0;
        local += cx * cy * sqrt((double)(adx * adx + ady * ady));
    }
    red[t] = local; __syncthreads();
    for (int s = 128; s; s >>= 1) { if (t < s) red[t] += red[t + s]; __syncthreads(); }
    __shared__ float inv_spa;
    if (t == 0) {
        double sig_spa = red[0] / ((double)SEQ * (double)SEQ);
        inv_spa = (float)(1.0 / (2.0 * sig_spa * sig_spa));
        double sig_spe = g_sum_spe / ((double)BATCH * (double)SEQ * (double)SEQ);
        g_inv2s2_spe = (float)(1.0 / (2.0 * sig_spe * sig_spe));
    }
    __syncthreads();
    float iv = inv_spa;
    for (int idx = t; idx < 64 * 64; idx += 256) {
        int adx = idx >> 6, ady = idx & 63;
        g_spa[idx] = expf(-sqrtf((float)(adx * adx + ady * ady)) * iv);
    }
}

// ---------------- fused masked flash attention (both heads/CTA) ----------------
// grid (64 row-tiles, BATCH), 256 threads, dyn smem = 138240 B
__global__ void __launch_bounds__(256, 1) k_flash() {
    extern __shared__ float sm[];
    float* qiT = sm;                      // [128][68]
    float* kjT = qiT + 128 * 68;          // [128][68]
    float* vs  = kjT + 128 * 68;          // [64][132]
    float* ps  = vs + 64 * 132;           // [2][64][68]
    int b  = blockIdx.y;
    int i0 = blockIdx.x * 64;
    int tid = threadIdx.x;
    int ty = tid >> 4, tx = tid & 15;
    int myhead = tx >> 3;
    int d0 = tx * 8;

    for (int idx = tid; idx < 64 * 128; idx += 256) {
        int r = idx >> 7, k = idx & 127;
        qiT[k * 68 + r] = g_q[(b * SEQ + i0 + r) * 128 + k];
    }
    float inv_spe = g_inv2s2_spe;
    float o[4][8] = {};
    float mrun[2][4], lrun[2][4];
    #pragma unroll
    for (int h = 0; h < 2; h++)
        #pragma unroll
        for (int i = 0; i < 4; i++) { mrun[h][i] = -1e30f; lrun[h][i] = 0.f; }
    int ig[4], gxi[4], gyi[4];
    #pragma unroll
    for (int i = 0; i < 4; i++) {
        ig[i] = i0 + 4 * ty + i; gxi[i] = ig[i] >> 6; gyi[i] = ig[i] & 63;
    }

    for (int jt = 0; jt < 64; jt++) {
        int j0 = jt * 64;
        __syncthreads();   // protect kjT/vs from previous PV reads (covers qiT on jt=0 via next sync)
        for (int idx = tid; idx < 64 * 128; idx += 256) {
            int r = idx >> 7, k = idx & 127;
            kjT[k * 68 + r]  = g_k[(b * SEQ + j0 + r) * 128 + k];
            vs[r * 132 + k]  = g_v[(b * SEQ + j0 + r) * 128 + k];
        }
        __syncthreads();

        float s0[4][4] = {}, s1[4][4] = {};
        #pragma unroll 4
        for (int k = 0; k < 64; k++) {
            float4 av = *(const float4*)&qiT[k * 68 + 4 * ty];
            float4 bv = *(const float4*)&kjT[k * 68 + 4 * tx];
            float a[4] = {av.x, av.y, av.z, av.w};
            float c[4] = {bv.x, bv.y, bv.z, bv.w};
            #pragma unroll
            for (int i = 0; i < 4; i++)
                #pragma unroll
                for (int j = 0; j < 4; j++) s0[i][j] = fmaf(a[i], c[j], s0[i][j]);
        }
        #pragma unroll 4
        for (int k = 64; k < 128; k++) {
            float4 av = *(const float4*)&qiT[k * 68 + 4 * ty];
            float4 bv = *(const float4*)&kjT[k * 68 + 4 * tx];
            float a[4] = {av.x, av.y, av.z, av.w};
            float c[4] = {bv.x, bv.y, bv.z, bv.w};
            #pragma unroll
            for (int i = 0; i < 4; i++)
                #pragma unroll
                for (int j = 0; j < 4; j++) s1[i][j] = fmaf(a[i], c[j], s1[i][j]);
        }

        // combined spectral * spatial mask for the 4x4 microtile
        float wm[4][4];
        #pragma unroll
        for (int i = 0; i < 4; i++) {
            size_t base = ((size_t)(b * SEQ + ig[i])) * SEQ + j0 + 4 * tx;
            const __half2* dp = (const __half2*)(g_dist + base);
            __half2 h0 = dp[0], h1 = dp[1];
            float dv[4] = { __low2float(h0), __high2float(h0),
                            __low2float(h1), __high2float(h1) };
            #pragma unroll
            for (int j = 0; j < 4; j++) {
                int jg = j0 + 4 * tx + j;
                int adx = abs(gxi[i] - (jg >> 6));
                int ady = abs(gyi[i] - (jg & 63));
                float spa = __ldg(&g_spa[adx * 64 + ady]);
                wm[i][j] = spa * __expf(-dv[j] * inv_spe);
            }
        }

        // online softmax per (head, row)
        #pragma unroll
        for (int h = 0; h < 2; h++) {
            float (*sp)[4] = h ? s1 : s0;
            #pragma unroll
            for (int i = 0; i < 4; i++) {
                float p[4]; float mx = -1e30f;
                #pragma unroll
                for (int j = 0; j < 4; j++) {
                    float sc = sp[i][j] * SCALE * wm[i][j];
                    p[j] = sc; mx = fmaxf(mx, sc);
                }
                #pragma unroll
                for (int off = 8; off; off >>= 1)
                    mx = fmaxf(mx, __shfl_xor_sync(0xffffffffu, mx, off));
                float mold = mrun[h][i];
                float mnew = fmaxf(mold, mx);
                float corr = __expf(mold - mnew);
                float rs = 0.f;
                #pragma unroll
                for (int j = 0; j < 4; j++) { p[j] = __expf(p[j] - mnew); rs += p[j]; }
                #pragma unroll
                for (int off = 8; off; off >>= 1)
                    rs += __shfl_xor_sync(0xffffffffu, rs, off);
                lrun[h][i] = lrun[h][i] * corr + rs;
                mrun[h][i] = mnew;
                float* pr = ps + (h * 64 + 4 * ty + i) * 68 + 4 * tx;
                pr[0] = p[0]; pr[1] = p[1]; pr[2] = p[2]; pr[3] = p[3];
                if (myhead == h) {
                    #pragma unroll
                    for (int d = 0; d < 8; d++) o[i][d] *= corr;
                }
            }
        }
        __syncthreads();

        // PV: o[r][d] += P[my head][r][k] * V[k][d]
        const float* psh = ps + myhead * 64 * 68;
        #pragma unroll 4
        for (int k = 0; k < 64; k++) {
            float4 v0 = *(const float4*)&vs[k * 132 + d0];
            float4 v1 = *(const float4*)&vs[k * 132 + d0 + 4];
            #pragma unroll
            for (int i = 0; i < 4; i++) {
                float pv = psh[(4 * ty + i) * 68 + k];
                o[i][0] = fmaf(pv, v0.x, o[i][0]);
                o[i][1] = fmaf(pv, v0.y, o[i][1]);
                o[i][2] = fmaf(pv, v0.z, o[i][2]);
                o[i][3] = fmaf(pv, v0.w, o[i][3]);
                o[i][4] = fmaf(pv, v1.x, o[i][4]);
                o[i][5] = fmaf(pv, v1.y, o[i][5]);
                o[i][6] = fmaf(pv, v1.z, o[i][6]);
                o[i][7] = fmaf(pv, v1.w, o[i][7]);
            }
        }
    }

    #pragma unroll
    for (int i = 0; i < 4; i++) {
        float linv = 1.f / lrun[myhead][i];
        float* dst = g_attn + (b * SEQ + ig[i]) * 128 + d0;
        #pragma unroll
        for (int d = 0; d < 8; d++) dst[d] = o[i][d] * linv;
    }
}

// ---------------- fused FFN: wn-linear -> exact GELU -> wn-linear ----------------
__global__ void k_ff(const float* __restrict__ b1, const float* __restrict__ b2,
                     float* __restrict__ out) {
    int token = blockIdx.x, t = threadIdx.x;
    __shared__ float s0[128], s1[128];
    s0[t] = g_attn[token * 128 + t];
    __syncthreads();
    const float* w1 = g_W + (384 + t) * 128;
    float acc = b1[t];
    #pragma unroll 16
    for (int k = 0; k < 128; k++) acc = fmaf(w1[k], s0[k], acc);
    s1[t] = 0.5f * acc * (1.0f + erff(acc * 0.70710678118654752f));
    __syncthreads();
    const float* w2 = g_W + (512 + t) * 128;
    float acc2 = b2[t];
    #pragma unroll 16
    for (int k = 0; k < 128; k++) acc2 = fmaf(w2[k], s1[k], acc2);
    out[token * 128 + t] = acc2;
}

// ---------------- launch ----------------
extern "C" void kernel_launch(void* const* d_in, const int* in_sizes, int n_in,
                              void* d_out, int out_size) {
    const float* x     = (const float*)d_in[0];
    const float* v_qkv = (const float*)d_in[1];
    const float* g_qkv = (const float*)d_in[2];
    const float* b_qkv = (const float*)d_in[3];
    const float* v_ff1 = (const float*)d_in[4];
    const float* g_ff1 = (const float*)d_in[5];
    const float* b_ff1 = (const float*)d_in[6];
    const float* v_ff2 = (const float*)d_in[7];
    const float* g_ff2 = (const float*)d_in[8];
    const float* b_ff2 = (const float*)d_in[9];
    float* out = (float*)d_out;

    cudaFuncSetAttribute(k_dist,  cudaFuncAttributeMaxDynamicSharedMemorySize, 2 * 128 * 68 * 4);
    cudaFuncSetAttribute(k_flash, cudaFuncAttributeMaxDynamicSharedMemorySize,
                         (128 * 68 + 128 * 68 + 64 * 132 + 2 * 64 * 68) * 4);

    k_init<<<1, 1>>>();
    k_weights<<<640, 128>>>(v_qkv, g_qkv, v_ff1, g_ff1, v_ff2, g_ff2);
    k_qkv<<<BATCH * SEQ, 128>>>(x, b_qkv);
    k_dist<<<dim3(64, 64, BATCH), 256, 2 * 128 * 68 * 4>>>(x);
    k_finalize<<<1, 256>>>();
    k_flash<<<dim3(64, BATCH), 256, (128 * 68 + 128 * 68 + 64 * 132 + 2 * 64 * 68) * 4>>>();
    k_ff<<<BATCH * SEQ, 128>>>(b_ff1, b_ff2, out);
}